// round 1
// baseline (speedup 1.0000x reference)
#include <cuda_runtime.h>
#include <cuda_bf16.h>
#include <cstdint>

// Problem constants
#define BB 2048   // batch
#define TT 64     // timesteps
#define HH 64     // LSTM hidden
#define GG 256    // 4*H gates
#define NL 8      // LSTM layers

// Ping-pong inter-layer buffers, layout [T, B, H] (layer0 input uses [T, B, 16])
__device__ float g_bufA[(size_t)TT * BB * HH + 256];
__device__ float g_bufB[(size_t)TT * BB * HH + 256];

__device__ __forceinline__ float* bufptr(int s) { return s ? g_bufB : g_bufA; }

__device__ __forceinline__ float sigm(float x) {
    return __fdividef(1.0f, 1.0f + __expf(-x));
}
__device__ __forceinline__ float tanh_(float x) {
    return __fdividef(2.0f, 1.0f + __expf(-2.0f * x)) - 1.0f;
}

// ---------------------------------------------------------------------------
// Input MLP: x[B,T,2] -> relu(x@w1^T+b1)@w2^T+b2 -> g_bufA as [T,B,16]
// ---------------------------------------------------------------------------
__global__ void mlp_in_kernel(const float* __restrict__ x,
                              const float* __restrict__ w1, const float* __restrict__ b1,
                              const float* __restrict__ w2, const float* __restrict__ b2)
{
    __shared__ float s_w1[16][2], s_b1[16], s_w2[16][16], s_b2[16];
    int tid = threadIdx.x;
    if (tid < 32) { s_w1[tid / 2][tid % 2] = w1[tid]; }
    if (tid < 16) { s_b1[tid] = b1[tid]; s_b2[tid] = b2[tid]; }
    if (tid >= 32 && tid < 32 + 256) {
        int i = tid - 32;
        s_w2[i / 16][i % 16] = w2[i];
    }
    __syncthreads();

    int idx = blockIdx.x * blockDim.x + tid;      // 0 .. B*T-1, idx = b*T + t
    int b = idx / TT;
    int t = idx % TT;
    float x0 = x[(size_t)idx * 2 + 0];
    float x1 = x[(size_t)idx * 2 + 1];

    float h1[16];
#pragma unroll
    for (int j = 0; j < 16; j++) {
        float v = fmaf(s_w1[j][0], x0, fmaf(s_w1[j][1], x1, s_b1[j]));
        h1[j] = fmaxf(v, 0.0f);
    }
    float* dst = g_bufA + (size_t)t * BB * 16 + (size_t)b * 16;
#pragma unroll
    for (int j = 0; j < 16; j++) {
        float o = s_b2[j];
#pragma unroll
        for (int k = 0; k < 16; k++) o = fmaf(s_w2[j][k], h1[k], o);
        dst[j] = o;
    }
}

// ---------------------------------------------------------------------------
// One LSTM layer. Each CTA owns 16 batch rows, scans all 64 timesteps.
// Thread j (0..255) owns gate column j; its I+64 weights live in registers
// for the whole layer. Gates exchanged through shared memory for the
// elementwise cell update.
// ---------------------------------------------------------------------------
template <int I>
__global__ void __launch_bounds__(256, 1)
lstm_kernel(int insel, int outsel,
            const float* __restrict__ w_ih, const float* __restrict__ w_hh,
            const float* __restrict__ b_ih, const float* __restrict__ b_hh)
{
    constexpr int BT = 16;                 // batch rows per CTA
    __shared__ float s_in[BT][I];          // staged x_t tile
    __shared__ float s_h[BT][HH];          // current hidden state
    __shared__ float s_c[BT][HH];          // cell state
    __shared__ float s_g[BT][GG];          // gate buffer

    const float* in  = bufptr(insel);
    float*       out = bufptr(outsel);
    const int tid = threadIdx.x;
    const int b0  = blockIdx.x * BT;

    // Per-thread weights in registers (persist across all 64 steps)
    float wi[I], wh[HH];
#pragma unroll
    for (int k = 0; k < I; k++)  wi[k] = w_ih[(size_t)tid * I + k];
#pragma unroll
    for (int k = 0; k < HH; k++) wh[k] = w_hh[(size_t)tid * HH + k];
    const float bias = b_ih[tid] + b_hh[tid];

    // h0 = c0 = 0
    for (int i = tid; i < BT * HH; i += 256) {
        (&s_h[0][0])[i] = 0.0f;
        (&s_c[0][0])[i] = 0.0f;
    }
    __syncthreads();

    for (int t = 0; t < TT; t++) {
        // stage x_t tile: contiguous BT*I floats at [t, b0, :]
        {
            const float4* src = reinterpret_cast<const float4*>(in + (size_t)t * BB * I + (size_t)b0 * I);
            float4* dst = reinterpret_cast<float4*>(&s_in[0][0]);
            for (int i = tid; i < BT * I / 4; i += 256) dst[i] = src[i];
        }
        __syncthreads();

        // gates = bias + x_t @ w_ih^T + h @ w_hh^T   (thread = one gate column)
        float acc[BT];
#pragma unroll
        for (int r = 0; r < BT; r++) acc[r] = bias;

#pragma unroll
        for (int k4 = 0; k4 < I; k4 += 4) {
#pragma unroll
            for (int r = 0; r < BT; r++) {
                float4 v = *reinterpret_cast<const float4*>(&s_in[r][k4]);  // broadcast
                acc[r] = fmaf(v.x, wi[k4 + 0], acc[r]);
                acc[r] = fmaf(v.y, wi[k4 + 1], acc[r]);
                acc[r] = fmaf(v.z, wi[k4 + 2], acc[r]);
                acc[r] = fmaf(v.w, wi[k4 + 3], acc[r]);
            }
        }
#pragma unroll
        for (int k4 = 0; k4 < HH; k4 += 4) {
#pragma unroll
            for (int r = 0; r < BT; r++) {
                float4 v = *reinterpret_cast<const float4*>(&s_h[r][k4]);   // broadcast
                acc[r] = fmaf(v.x, wh[k4 + 0], acc[r]);
                acc[r] = fmaf(v.y, wh[k4 + 1], acc[r]);
                acc[r] = fmaf(v.z, wh[k4 + 2], acc[r]);
                acc[r] = fmaf(v.w, wh[k4 + 3], acc[r]);
            }
        }

#pragma unroll
        for (int r = 0; r < BT; r++) s_g[r][tid] = acc[r];
        __syncthreads();

        // elementwise update: 4 (row, unit) pairs per thread
#pragma unroll
        for (int p = 0; p < 4; p++) {
            int ul = p * 256 + tid;
            int r  = ul >> 6;
            int u  = ul & 63;
            float gi = s_g[r][u];
            float gf = s_g[r][64 + u];
            float gg = s_g[r][128 + u];
            float go = s_g[r][192 + u];
            float iv = sigm(gi);
            float fv = sigm(gf);
            float gv = tanh_(gg);
            float ov = sigm(go);
            float c  = fmaf(fv, s_c[r][u], iv * gv);
            float h  = ov * tanh_(c);
            s_c[r][u] = c;
            s_h[r][u] = h;
            out[(size_t)t * BB * HH + (size_t)(b0 + r) * HH + u] = h;
        }
        __syncthreads();   // protects s_h / s_g for next step
    }
}

// ---------------------------------------------------------------------------
// Output MLP: h[T,B,64] -> relu(h@wo1^T+bo1)@wo2^T+bo2 -> out[B,T,4]
// ---------------------------------------------------------------------------
__global__ void mlp_out_kernel(int insel,
                               const float* __restrict__ wo1, const float* __restrict__ bo1,
                               const float* __restrict__ wo2, const float* __restrict__ bo2,
                               float* __restrict__ outp)
{
    __shared__ float s_w1[32][64];   // 8 KB
    __shared__ float s_b1[32];
    __shared__ float s_w2[4][32];
    __shared__ float s_b2[4];
    int tid = threadIdx.x;
    for (int i = tid; i < 32 * 64; i += 256) s_w1[i / 64][i % 64] = wo1[i];
    if (tid < 32) s_b1[tid] = bo1[tid];
    if (tid < 128) s_w2[tid / 32][tid % 32] = wo2[tid];
    if (tid < 4) s_b2[tid] = bo2[tid];
    __syncthreads();

    const float* in = bufptr(insel);
    int idx = blockIdx.x * blockDim.x + tid;   // idx = t*B + b (coalesced h reads)
    int t = idx / BB;
    int b = idx % BB;

    float h[64];
    const float4* src = reinterpret_cast<const float4*>(in + (size_t)idx * HH);
#pragma unroll
    for (int i = 0; i < 16; i++) {
        float4 v = src[i];
        h[4 * i + 0] = v.x; h[4 * i + 1] = v.y; h[4 * i + 2] = v.z; h[4 * i + 3] = v.w;
    }

    float h2[32];
#pragma unroll
    for (int j = 0; j < 32; j++) {
        float o = s_b1[j];
#pragma unroll
        for (int k = 0; k < 64; k++) o = fmaf(s_w1[j][k], h[k], o);
        h2[j] = fmaxf(o, 0.0f);
    }
    float* dst = outp + ((size_t)b * TT + t) * 4;
#pragma unroll
    for (int j = 0; j < 4; j++) {
        float o = s_b2[j];
#pragma unroll
        for (int k = 0; k < 32; k++) o = fmaf(s_w2[j][k], h2[k], o);
        dst[j] = o;
    }
}

// ---------------------------------------------------------------------------
extern "C" void kernel_launch(void* const* d_in, const int* in_sizes, int n_in,
                              void* d_out, int out_size)
{
    const float* x     = (const float*)d_in[0];
    const float* w1    = (const float*)d_in[1];
    const float* b1    = (const float*)d_in[2];
    const float* w2    = (const float*)d_in[3];
    const float* b2    = (const float*)d_in[4];
    const float* w_ih0 = (const float*)d_in[5];
    const float* w_hh0 = (const float*)d_in[6];
    const float* b_ih0 = (const float*)d_in[7];
    const float* b_hh0 = (const float*)d_in[8];
    const float* w_ih  = (const float*)d_in[9];   // (7, 256, 64)
    const float* w_hh  = (const float*)d_in[10];  // (7, 256, 64)
    const float* b_ih  = (const float*)d_in[11];  // (7, 256)
    const float* b_hh  = (const float*)d_in[12];  // (7, 256)
    const float* wo1   = (const float*)d_in[13];
    const float* bo1   = (const float*)d_in[14];
    const float* wo2   = (const float*)d_in[15];
    const float* bo2   = (const float*)d_in[16];
    float* outp = (float*)d_out;

    const int nelem = BB * TT;            // 131072
    mlp_in_kernel<<<nelem / 256, 256>>>(x, w1, b1, w2, b2);

    // layer 0: A(stride16) -> B
    lstm_kernel<16><<<BB / 16, 256>>>(0, 1, w_ih0, w_hh0, b_ih0, b_hh0);

    // layers 1..7: ping-pong B->A->B->...
    int cur = 1;
    for (int l = 0; l < NL - 1; l++) {
        int nxt = cur ^ 1;
        lstm_kernel<64><<<BB / 16, 256>>>(cur, nxt,
                                          w_ih + (size_t)l * GG * HH,
                                          w_hh + (size_t)l * GG * HH,
                                          b_ih + (size_t)l * GG,
                                          b_hh + (size_t)l * GG);
        cur = nxt;
    }

    mlp_out_kernel<<<nelem / 256, 256>>>(cur, wo1, bo1, wo2, bo2, outp);
}

// round 2
// speedup vs baseline: 1.2157x; 1.2157x over previous
#include <cuda_runtime.h>
#include <cuda_bf16.h>
#include <cstdint>

// Problem constants
#define BB 2048   // batch
#define BP 2058   // padded batch (147 CTAs * 14 rows)
#define TT 64     // timesteps
#define HH 64     // LSTM hidden
#define GG 256    // 4*H gates
#define NL 8      // LSTM layers
#define BT 14     // batch rows per CTA
#define NCTA 147  // ceil(2048/14)

// Ping-pong inter-layer buffers, layout [T, BP, H] (layer0 input uses [T, BP, 16])
__device__ float g_bufA[(size_t)TT * BP * HH + 256];
__device__ float g_bufB[(size_t)TT * BP * HH + 256];

__device__ __forceinline__ float* bufptr(int s) { return s ? g_bufB : g_bufA; }

__device__ __forceinline__ float sigm(float x) {
    return __fdividef(1.0f, 1.0f + __expf(-x));
}
__device__ __forceinline__ float tanh_(float x) {
    return __fdividef(2.0f, 1.0f + __expf(-2.0f * x)) - 1.0f;
}

// ---- packed f32x2 helpers (Blackwell FFMA2; PTX-only, ptxas won't auto-fuse) ----
__device__ __forceinline__ void ffma2(uint64_t& d, uint64_t a, uint64_t b) {
    asm("fma.rn.f32x2 %0, %1, %2, %0;" : "+l"(d) : "l"(a), "l"(b));
}
__device__ __forceinline__ uint64_t pack2(float lo, float hi) {
    uint64_t r;
    asm("mov.b64 %0, {%1, %2};" : "=l"(r) : "f"(lo), "f"(hi));
    return r;
}
__device__ __forceinline__ float hsum2(uint64_t v) {
    float lo, hi;
    asm("mov.b64 {%0, %1}, %2;" : "=f"(lo), "=f"(hi) : "l"(v));
    return lo + hi;
}

// ---------------------------------------------------------------------------
// Input MLP: x[B,T,2] -> relu(x@w1^T+b1)@w2^T+b2 -> g_bufA as [T,BP,16]
// ---------------------------------------------------------------------------
__global__ void mlp_in_kernel(const float* __restrict__ x,
                              const float* __restrict__ w1, const float* __restrict__ b1,
                              const float* __restrict__ w2, const float* __restrict__ b2)
{
    __shared__ float s_w1[16][2], s_b1[16], s_w2[16][16], s_b2[16];
    int tid = threadIdx.x;
    if (tid < 32) { s_w1[tid / 2][tid % 2] = w1[tid]; }
    if (tid < 16) { s_b1[tid] = b1[tid]; s_b2[tid] = b2[tid]; }
    if (tid >= 32 && tid < 32 + 256) {
        int i = tid - 32;
        s_w2[i / 16][i % 16] = w2[i];
    }
    __syncthreads();

    int idx = blockIdx.x * blockDim.x + tid;      // 0 .. B*T-1, idx = b*T + t
    int b = idx / TT;
    int t = idx % TT;
    float x0 = x[(size_t)idx * 2 + 0];
    float x1 = x[(size_t)idx * 2 + 1];

    float h1[16];
#pragma unroll
    for (int j = 0; j < 16; j++) {
        float v = fmaf(s_w1[j][0], x0, fmaf(s_w1[j][1], x1, s_b1[j]));
        h1[j] = fmaxf(v, 0.0f);
    }
    float* dst = g_bufA + (size_t)t * BP * 16 + (size_t)b * 16;
#pragma unroll
    for (int j = 0; j < 16; j++) {
        float o = s_b2[j];
#pragma unroll
        for (int k = 0; k < 16; k++) o = fmaf(s_w2[j][k], h1[k], o);
        dst[j] = o;
    }
}

// ---------------------------------------------------------------------------
// One LSTM layer. Each CTA owns BT=14 batch rows, scans all 64 timesteps.
// Thread j (0..255) owns gate column j; its (I+64)/2 weight PAIRS live in
// 64-bit registers for the whole layer. Mainloop is FFMA2 (f32x2) with the
// accumulator holding {sum over even k, sum over odd k}; horizontal add at
// the end. Activation pairs come from LDS.128 (ulonglong2) broadcasts.
// ---------------------------------------------------------------------------
template <int I>
__global__ void __launch_bounds__(256, 1)
lstm_kernel(int insel, int outsel,
            const float* __restrict__ w_ih, const float* __restrict__ w_hh,
            const float* __restrict__ b_ih, const float* __restrict__ b_hh)
{
    __shared__ __align__(16) float s_in[BT][I];   // staged x_t tile
    __shared__ __align__(16) float s_h[BT][HH];   // current hidden state
    __shared__ __align__(16) float s_c[BT][HH];   // cell state
    __shared__ __align__(16) float s_g[BT][GG];   // gate buffer

    const float* in  = bufptr(insel);
    float*       out = bufptr(outsel);
    const int tid = threadIdx.x;
    const int b0  = blockIdx.x * BT;

    // Per-thread weight pairs in 64-bit registers (persist across all 64 steps)
    uint64_t wi2[I / 2], wh2[HH / 2];
    {
        const uint64_t* wp = reinterpret_cast<const uint64_t*>(w_ih) + (size_t)tid * (I / 2);
#pragma unroll
        for (int k = 0; k < I / 2; k++) wi2[k] = wp[k];
        const uint64_t* hp = reinterpret_cast<const uint64_t*>(w_hh) + (size_t)tid * (HH / 2);
#pragma unroll
        for (int k = 0; k < HH / 2; k++) wh2[k] = hp[k];
    }
    const uint64_t bias2 = pack2(b_ih[tid] + b_hh[tid], 0.0f);

    // h0 = c0 = 0
    for (int i = tid; i < BT * HH; i += 256) {
        (&s_h[0][0])[i] = 0.0f;
        (&s_c[0][0])[i] = 0.0f;
    }
    __syncthreads();

    for (int t = 0; t < TT; t++) {
        // stage x_t tile: contiguous BT*I floats at [t, b0, :]
        {
            const float4* src = reinterpret_cast<const float4*>(in + (size_t)t * BP * I + (size_t)b0 * I);
            float4* dst = reinterpret_cast<float4*>(&s_in[0][0]);
            for (int i = tid; i < BT * I / 4; i += 256) dst[i] = src[i];
        }
        __syncthreads();

        // gates = bias + x_t @ w_ih^T + h @ w_hh^T   (thread = one gate column)
        uint64_t acc[BT];
#pragma unroll
        for (int r = 0; r < BT; r++) acc[r] = bias2;

#pragma unroll
        for (int k4 = 0; k4 < I; k4 += 4) {
#pragma unroll
            for (int r = 0; r < BT; r++) {
                ulonglong2 v = *reinterpret_cast<const ulonglong2*>(&s_in[r][k4]);  // LDS.128 broadcast
                ffma2(acc[r], v.x, wi2[k4 / 2]);
                ffma2(acc[r], v.y, wi2[k4 / 2 + 1]);
            }
        }
#pragma unroll
        for (int k4 = 0; k4 < HH; k4 += 4) {
#pragma unroll
            for (int r = 0; r < BT; r++) {
                ulonglong2 v = *reinterpret_cast<const ulonglong2*>(&s_h[r][k4]);   // LDS.128 broadcast
                ffma2(acc[r], v.x, wh2[k4 / 2]);
                ffma2(acc[r], v.y, wh2[k4 / 2 + 1]);
            }
        }

#pragma unroll
        for (int r = 0; r < BT; r++) s_g[r][tid] = hsum2(acc[r]);
        __syncthreads();

        // elementwise update: BT*64 = 896 (row, unit) pairs over 256 threads
#pragma unroll
        for (int p = 0; p < 4; p++) {
            int ul = p * 256 + tid;
            if (ul < BT * HH) {
                int r  = ul >> 6;
                int u  = ul & 63;
                float gi = s_g[r][u];
                float gf = s_g[r][64 + u];
                float gg = s_g[r][128 + u];
                float go = s_g[r][192 + u];
                float iv = sigm(gi);
                float fv = sigm(gf);
                float gv = tanh_(gg);
                float ov = sigm(go);
                float c  = fmaf(fv, s_c[r][u], iv * gv);
                float h  = ov * tanh_(c);
                s_c[r][u] = c;
                s_h[r][u] = h;
                out[(size_t)t * BP * HH + (size_t)(b0 + r) * HH + u] = h;
            }
        }
        __syncthreads();   // protects s_h / s_g for next step
    }
}

// ---------------------------------------------------------------------------
// Output MLP: h[T,BP,64] -> relu(h@wo1^T+bo1)@wo2^T+bo2 -> out[B,T,4]
// ---------------------------------------------------------------------------
__global__ void mlp_out_kernel(int insel,
                               const float* __restrict__ wo1, const float* __restrict__ bo1,
                               const float* __restrict__ wo2, const float* __restrict__ bo2,
                               float* __restrict__ outp)
{
    __shared__ float s_w1[32][64];   // 8 KB
    __shared__ float s_b1[32];
    __shared__ float s_w2[4][32];
    __shared__ float s_b2[4];
    int tid = threadIdx.x;
    for (int i = tid; i < 32 * 64; i += 256) s_w1[i / 64][i % 64] = wo1[i];
    if (tid < 32) s_b1[tid] = bo1[tid];
    if (tid < 128) s_w2[tid / 32][tid % 32] = wo2[tid];
    if (tid < 4) s_b2[tid] = bo2[tid];
    __syncthreads();

    const float* in = bufptr(insel);
    int idx = blockIdx.x * blockDim.x + tid;   // idx = t*B + b (coalesced h reads)
    int t = idx / BB;
    int b = idx % BB;

    float h[64];
    const float4* src = reinterpret_cast<const float4*>(in + ((size_t)t * BP + b) * HH);
#pragma unroll
    for (int i = 0; i < 16; i++) {
        float4 v = src[i];
        h[4 * i + 0] = v.x; h[4 * i + 1] = v.y; h[4 * i + 2] = v.z; h[4 * i + 3] = v.w;
    }

    float h2[32];
#pragma unroll
    for (int j = 0; j < 32; j++) {
        float o = s_b1[j];
#pragma unroll
        for (int k = 0; k < 64; k++) o = fmaf(s_w1[j][k], h[k], o);
        h2[j] = fmaxf(o, 0.0f);
    }
    float* dst = outp + ((size_t)b * TT + t) * 4;
#pragma unroll
    for (int j = 0; j < 4; j++) {
        float o = s_b2[j];
#pragma unroll
        for (int k = 0; k < 32; k++) o = fmaf(s_w2[j][k], h2[k], o);
        dst[j] = o;
    }
}

// ---------------------------------------------------------------------------
extern "C" void kernel_launch(void* const* d_in, const int* in_sizes, int n_in,
                              void* d_out, int out_size)
{
    const float* x     = (const float*)d_in[0];
    const float* w1    = (const float*)d_in[1];
    const float* b1    = (const float*)d_in[2];
    const float* w2    = (const float*)d_in[3];
    const float* b2    = (const float*)d_in[4];
    const float* w_ih0 = (const float*)d_in[5];
    const float* w_hh0 = (const float*)d_in[6];
    const float* b_ih0 = (const float*)d_in[7];
    const float* b_hh0 = (const float*)d_in[8];
    const float* w_ih  = (const float*)d_in[9];   // (7, 256, 64)
    const float* w_hh  = (const float*)d_in[10];  // (7, 256, 64)
    const float* b_ih  = (const float*)d_in[11];  // (7, 256)
    const float* b_hh  = (const float*)d_in[12];  // (7, 256)
    const float* wo1   = (const float*)d_in[13];
    const float* bo1   = (const float*)d_in[14];
    const float* wo2   = (const float*)d_in[15];
    const float* bo2   = (const float*)d_in[16];
    float* outp = (float*)d_out;

    const int nelem = BB * TT;            // 131072
    mlp_in_kernel<<<nelem / 256, 256>>>(x, w1, b1, w2, b2);

    // layer 0: A(stride16) -> B
    lstm_kernel<16><<<NCTA, 256>>>(0, 1, w_ih0, w_hh0, b_ih0, b_hh0);

    // layers 1..7: ping-pong B->A->B->...
    int cur = 1;
    for (int l = 0; l < NL - 1; l++) {
        int nxt = cur ^ 1;
        lstm_kernel<64><<<NCTA, 256>>>(cur, nxt,
                                       w_ih + (size_t)l * GG * HH,
                                       w_hh + (size_t)l * GG * HH,
                                       b_ih + (size_t)l * GG,
                                       b_hh + (size_t)l * GG);
        cur = nxt;
    }

    mlp_out_kernel<<<nelem / 256, 256>>>(cur, wo1, bo1, wo2, bo2, outp);
}